// round 11
// baseline (speedup 1.0000x reference)
#include <cuda_runtime.h>
#include <cuda_fp16.h>
#include <math.h>
#include <float.h>
#include <stdint.h>

// Problem shape (fixed)
#define Dh    1024
#define NB    256
#define NA    512
#define KSEL  64
#define SEL   128
#define NPART 16       // gemm N-chunks of 64
#define NK16  64       // Dh / 16

// Scratch (device globals)
__device__ int   g_idx[NB * SEL];
__device__ float g_part[NPART * NB * SEL];
// fp16 operands in m16n8k16 fragment layout:
//  A (single fp16): [b][k16(64)][mf(8)][lane(32)] -> uint4 {a0,a1,a2,a3}  (67 MB)
//  B (hi/lo split): [k16(64)][nfg(128)][lane(32)] -> uint4 {bh0,bh1,bl0,bl1} (4 MB)
__device__ uint4 g_Af[NB * NK16 * 8 * 32];
__device__ uint4 g_Bf[NK16 * 128 * 32];

// ---------------------------------------------------------------------------
__device__ __forceinline__ uint32_t pack_h(float x0, float x1) {
    const __half2 h = __floats2half2_rn(x0, x1);
    return *(const uint32_t*)&h;
}
__device__ __forceinline__ uint32_t pack_h_lo(uint32_t hi_pack, float x0, float x1) {
    const __half2 h = *(const __half2*)&hi_pack;
    const float2 f = __half22float2(h);
    return pack_h(x0 - f.x, x1 - f.y);
}
__device__ __forceinline__ float fast_tanh(float x) {
    float r;
    asm("tanh.approx.f32 %0, %1;" : "=f"(r) : "f"(x));
    return r;
}

__device__ __forceinline__ void mma_f16(float* d, const uint32_t* a,
                                        uint32_t b0, uint32_t b1) {
    asm volatile(
        "mma.sync.aligned.m16n8k16.row.col.f32.f16.f16.f32 "
        "{%0,%1,%2,%3}, {%4,%5,%6,%7}, {%8,%9}, {%0,%1,%2,%3};"
        : "+f"(d[0]), "+f"(d[1]), "+f"(d[2]), "+f"(d[3])
        : "r"(a[0]), "r"(a[1]), "r"(a[2]), "r"(a[3]), "r"(b0), "r"(b1));
}

// ---------------------------------------------------------------------------
// Kernel 1: centroids + masked distances + bitonic top-64.
// Grid (NB, 2): blockIdx.y picks which selection this block computes.
// ---------------------------------------------------------------------------
__global__ void __launch_bounds__(NA) select_kernel(const float* __restrict__ coords,
                                                   const void*  __restrict__ ligp) {
    const int b    = blockIdx.x;
    const int pass = blockIdx.y;
    const int t    = threadIdx.x;

    __shared__ float sv[NA];
    __shared__ int   si[NA];
    __shared__ float s_warp[16][7];
    __shared__ float s_cent[6];

    const float* fl = (const float*)ligp;
    const unsigned char* ul = (const unsigned char*)ligp;
    const int mode = (fl[0] == 1.0f) ? 2 : ((ul[1] != 0) ? 0 : 1);

    const int a = b * NA + t;
    const float cx = coords[(size_t)a * 3 + 0];
    const float cy = coords[(size_t)a * 3 + 1];
    const float cz = coords[(size_t)a * 3 + 2];

    bool lig;
    if (mode == 0)      lig = ul[a] != 0;
    else if (mode == 1) lig = ((const int*)ligp)[a] != 0;
    else                lig = fl[a] != 0.0f;
    const float w = lig ? 1.0f : 0.0f;

    float r[7];
    r[0] = cx * w;          r[1] = cy * w;          r[2] = cz * w;
    r[3] = cx * (1.f - w);  r[4] = cy * (1.f - w);  r[5] = cz * (1.f - w);
    r[6] = w;

    #pragma unroll
    for (int o = 16; o > 0; o >>= 1) {
        #pragma unroll
        for (int i = 0; i < 7; i++)
            r[i] += __shfl_down_sync(0xffffffff, r[i], o);
    }
    if ((t & 31) == 0) {
        #pragma unroll
        for (int i = 0; i < 7; i++) s_warp[t >> 5][i] = r[i];
    }
    __syncthreads();
    if (t == 0) {
        float s[7];
        #pragma unroll
        for (int i = 0; i < 7; i++) s[i] = 0.f;
        for (int wI = 0; wI < 16; wI++) {
            #pragma unroll
            for (int i = 0; i < 7; i++) s[i] += s_warp[wI][i];
        }
        const float cl = s[6];
        const float cp = (float)NA - cl;
        s_cent[0] = s[0] / cl;  s_cent[1] = s[1] / cl;  s_cent[2] = s[2] / cl;
        s_cent[3] = s[3] / cp;  s_cent[4] = s[4] / cp;  s_cent[5] = s[5] / cp;
    }
    __syncthreads();

    float dsel;
    if (pass == 0) {
        const float dx = cx - s_cent[0], dy = cy - s_cent[1], dz = cz - s_cent[2];
        const float d = sqrtf(dx * dx + dy * dy + dz * dz);
        dsel = lig ? FLT_MAX : d;
    } else {
        const float dx = cx - s_cent[3], dy = cy - s_cent[4], dz = cz - s_cent[5];
        const float d = sqrtf(dx * dx + dy * dy + dz * dz);
        dsel = lig ? d : FLT_MAX;
    }

    sv[t] = dsel;
    si[t] = t;
    __syncthreads();
    #pragma unroll 1
    for (int k = 2; k <= NA; k <<= 1) {
        #pragma unroll 1
        for (int j = k >> 1; j > 0; j >>= 1) {
            const int ixj = t ^ j;
            const float v0 = sv[t];
            const float v1 = sv[ixj];
            const int   i1 = si[ixj];
            const bool up = ((t & k) == 0);
            const bool takeOther = ((t < ixj) == up) ? (v0 > v1) : (v0 < v1);
            __syncthreads();
            if (takeOther) { sv[t] = v1; si[t] = i1; }
            __syncthreads();
        }
    }
    if (t < KSEL) g_idx[b * SEL + pass * KSEL + t] = b * NA + si[t];
}

// ---------------------------------------------------------------------------
// Kernel 2a: W -> B fragment layout (fp16 hi/lo packed per uint4)
// ---------------------------------------------------------------------------
__global__ void __launch_bounds__(256) conv_w_kernel(const float* __restrict__ W) {
    const int idx  = blockIdx.x * 256 + threadIdx.x;   // < NK16*128*32
    const int lane = idx & 31;
    const int nfg  = (idx >> 5) & 127;
    const int k16  = idx >> 12;

    const int n  = nfg * 8 + (lane >> 2);
    const int k0 = k16 * 16 + (lane & 3) * 2;
    const float2 x0 = *(const float2*)(W + (size_t)n * Dh + k0);
    const float2 x1 = *(const float2*)(W + (size_t)n * Dh + k0 + 8);

    uint4 o;
    o.x = pack_h(x0.x, x0.y);
    o.y = pack_h(x1.x, x1.y);
    o.z = pack_h_lo(o.x, x0.x, x0.y);
    o.w = pack_h_lo(o.y, x1.x, x1.y);
    g_Bf[idx] = o;
}

// ---------------------------------------------------------------------------
// Kernel 2b: gather selected h rows -> A fragment layout (single fp16)
// ---------------------------------------------------------------------------
__global__ void __launch_bounds__(256) conv_h_kernel(const float* __restrict__ h) {
    const int idx  = blockIdx.x * 256 + threadIdx.x;   // < NB*NK16*8*32
    const int lane = idx & 31;
    const int mf   = (idx >> 5) & 7;
    const int k16  = (idx >> 8) & 63;
    const int b    = idx >> 14;

    const int r0 = mf * 16 + (lane >> 2);
    const int gr0 = g_idx[b * SEL + r0];
    const int gr1 = g_idx[b * SEL + r0 + 8];
    const int k0 = k16 * 16 + (lane & 3) * 2;

    const float2 x00 = *(const float2*)(h + (size_t)gr0 * Dh + k0);
    const float2 x10 = *(const float2*)(h + (size_t)gr1 * Dh + k0);
    const float2 x01 = *(const float2*)(h + (size_t)gr0 * Dh + k0 + 8);
    const float2 x11 = *(const float2*)(h + (size_t)gr1 * Dh + k0 + 8);

    uint4 o;
    o.x = pack_h(x00.x, x00.y);
    o.y = pack_h(x10.x, x10.y);
    o.z = pack_h(x01.x, x01.y);
    o.w = pack_h(x11.x, x11.y);
    g_Af[idx] = o;
}

// ---------------------------------------------------------------------------
// Kernel 3: fp16 2-product tensor GEMM + tanh + v-dot.
// 256 threads = 8 warps (wm 0..3 x wn 0..1), warp tile 32x32, block tile
// 128x64, grid (16, 256). __launch_bounds__(256,3) -> 3 co-resident blocks/SM
// = 6 warps/SMSP of independent drift to cover load-head latency.
// ---------------------------------------------------------------------------
__global__ void __launch_bounds__(256, 3) gemm_kernel(const float* __restrict__ bias,
                                                      const float* __restrict__ vvec) {
    const int ecp  = blockIdx.x;   // 0..15 (64-wide col chunk)
    const int b    = blockIdx.y;
    const int tid  = threadIdx.x;
    const int lane = tid & 31;
    const int wid  = tid >> 5;     // 0..7
    const int wm   = wid >> 1;     // 0..3
    const int wn   = wid & 1;      // 0..1

    __shared__ float s_b[64];
    __shared__ float s_v[64];
    __shared__ float s_part[2][128];

    if (tid < 64) {
        s_b[tid] = bias[ecp * 64 + tid];
        s_v[tid] = vvec[ecp * 64 + tid];
    }
    __syncthreads();

    const uint4* pA = g_Af + ((size_t)b * NK16 * 8 + wm * 2) * 32 + lane;
    const uint4* pB = g_Bf + ((size_t)(ecp * 8 + wn * 4)) * 32 + lane;

    float acc[2][4][4];
    #pragma unroll
    for (int mf = 0; mf < 2; mf++)
        #pragma unroll
        for (int nf = 0; nf < 4; nf++)
            #pragma unroll
            for (int r = 0; r < 4; r++) acc[mf][nf][r] = 0.f;

    #pragma unroll 1
    for (int k16 = 0; k16 < NK16; k16++) {
        uint32_t af[2][4];
        uint4 bb[4];
        #pragma unroll
        for (int mf = 0; mf < 2; mf++)
            *(uint4*)af[mf] = __ldg(pA + mf * 32);
        #pragma unroll
        for (int nf = 0; nf < 4; nf++)
            bb[nf] = __ldg(pB + nf * 32);

        // pass 1: A * B_hi  (8 independent accumulators)
        #pragma unroll
        for (int nf = 0; nf < 4; nf++)
            #pragma unroll
            for (int mf = 0; mf < 2; mf++)
                mma_f16(acc[mf][nf], af[mf], bb[nf].x, bb[nf].y);
        // pass 2: A * B_lo
        #pragma unroll
        for (int nf = 0; nf < 4; nf++)
            #pragma unroll
            for (int mf = 0; mf < 2; mf++)
                mma_f16(acc[mf][nf], af[mf], bb[nf].z, bb[nf].w);

        pA += 8 * 32;
        pB += 128 * 32;
    }

    // Epilogue: part[row] = sum_cols v[col]*tanh(acc + b[col])
    #pragma unroll
    for (int mf = 0; mf < 2; mf++) {
        float s0 = 0.f, s1 = 0.f;
        #pragma unroll
        for (int nf = 0; nf < 4; nf++) {
            const int cl = wn * 32 + nf * 8 + (lane & 3) * 2;
            s0 += s_v[cl]     * fast_tanh(acc[mf][nf][0] + s_b[cl]);
            s0 += s_v[cl + 1] * fast_tanh(acc[mf][nf][1] + s_b[cl + 1]);
            s1 += s_v[cl]     * fast_tanh(acc[mf][nf][2] + s_b[cl]);
            s1 += s_v[cl + 1] * fast_tanh(acc[mf][nf][3] + s_b[cl + 1]);
        }
        s0 += __shfl_xor_sync(0xffffffff, s0, 1);
        s0 += __shfl_xor_sync(0xffffffff, s0, 2);
        s1 += __shfl_xor_sync(0xffffffff, s1, 1);
        s1 += __shfl_xor_sync(0xffffffff, s1, 2);
        if ((lane & 3) == 0) {
            const int r = wm * 32 + mf * 16 + (lane >> 2);
            s_part[wn][r]     = s0;
            s_part[wn][r + 8] = s1;
        }
    }
    __syncthreads();

    if (tid < 128) {
        const float s = s_part[0][tid] + s_part[1][tid];
        g_part[((size_t)ecp * NB + b) * SEL + tid] = s;
    }
}

// ---------------------------------------------------------------------------
// Kernel 4: softmax + alpha-weighted gather sum.
// Grid (NB, 2), 128 threads: blockIdx.y picks which 512-dim half this block
// pools (softmax recomputed redundantly; doubles gather parallelism).
// ---------------------------------------------------------------------------
__global__ void __launch_bounds__(128) pool_kernel(const float* __restrict__ h,
                                                   float* __restrict__ out) {
    const int b  = blockIdx.x;
    const int hy = blockIdx.y;    // 0..1
    const int t  = threadIdx.x;   // 0..127

    __shared__ float s_al[SEL];
    __shared__ int   s_ix[SEL];
    __shared__ float s_tmp[2];

    {
        float s = 0.f;
        #pragma unroll
        for (int c = 0; c < NPART; c++)
            s += g_part[((size_t)c * NB + b) * SEL + t];
        s_al[t] = s;
        s_ix[t] = g_idx[b * SEL + t];
    }
    __syncthreads();
    if (t == 0) {
        float m = -FLT_MAX;
        for (int k = 0; k < SEL; k++) m = fmaxf(m, s_al[k]);
        s_tmp[0] = m;
    }
    __syncthreads();
    s_al[t] = expf(s_al[t] - s_tmp[0]);
    __syncthreads();
    if (t == 0) {
        float s = 0.f;
        for (int k = 0; k < SEL; k++) s += s_al[k];
        s_tmp[1] = 1.f / s;
    }
    __syncthreads();
    s_al[t] *= s_tmp[1];
    __syncthreads();

    const int d0 = hy * 512 + t * 4;
    float4 acc = make_float4(0.f, 0.f, 0.f, 0.f);
    #pragma unroll 8
    for (int k = 0; k < SEL; k++) {
        const float al = s_al[k];
        const float4 hv = __ldg((const float4*)(h + (size_t)s_ix[k] * Dh + d0));
        acc.x += al * hv.x;  acc.y += al * hv.y;
        acc.z += al * hv.z;  acc.w += al * hv.w;
    }
    *(float4*)(out + (size_t)b * Dh + d0) = acc;
}

// ---------------------------------------------------------------------------
extern "C" void kernel_launch(void* const* d_in, const int* in_sizes, int n_in,
                              void* d_out, int out_size) {
    const float* h      = (const float*)d_in[0];
    const float* coords = (const float*)d_in[1];
    const void*  lig    = d_in[3];
    const float* W      = (const float*)d_in[4];
    const float* bias   = (const float*)d_in[5];
    const float* vvec   = (const float*)d_in[6];
    float* out = (float*)d_out;

    dim3 gsel(NB, 2);
    select_kernel<<<gsel, NA>>>(coords, lig);
    conv_w_kernel<<<(NK16 * 128 * 32) / 256, 256>>>(W);
    conv_h_kernel<<<(NB * NK16 * 8 * 32) / 256, 256>>>(h);
    dim3 g3(NPART, NB);
    gemm_kernel<<<g3, 256>>>(bias, vvec);
    dim3 g4(NB, 2);
    pool_kernel<<<g4, 128>>>(h, out);
}

// round 12
// speedup vs baseline: 1.0931x; 1.0931x over previous
#include <cuda_runtime.h>
#include <cuda_fp16.h>
#include <math.h>
#include <float.h>
#include <stdint.h>

// Problem shape (fixed)
#define Dh    1024
#define NB    256
#define NA    512
#define KSEL  64
#define SEL   128
#define NPART 8        // gemm N-chunks of 128
#define NK16  64       // Dh / 16

// Scratch (device globals)
__device__ int   g_idx[NB * SEL];
__device__ float g_part[NPART * NB * SEL];
// fp16 operands in m16n8k16 fragment layout:
//  A (single fp16): [b][k16(64)][mf(8)][lane(32)] -> uint4 {a0,a1,a2,a3}  (67 MB)
//  B (hi/lo split): [k16(64)][nfg(128)][lane(32)] -> uint4 {bh0,bh1,bl0,bl1} (4 MB)
__device__ uint4 g_Af[NB * NK16 * 8 * 32];
__device__ uint4 g_Bf[NK16 * 128 * 32];

// ---------------------------------------------------------------------------
__device__ __forceinline__ uint32_t pack_h(float x0, float x1) {
    const __half2 h = __floats2half2_rn(x0, x1);
    return *(const uint32_t*)&h;
}
__device__ __forceinline__ uint32_t pack_h_lo(uint32_t hi_pack, float x0, float x1) {
    const __half2 h = *(const __half2*)&hi_pack;
    const float2 f = __half22float2(h);
    return pack_h(x0 - f.x, x1 - f.y);
}
__device__ __forceinline__ float fast_tanh(float x) {
    float r;
    asm("tanh.approx.f32 %0, %1;" : "=f"(r) : "f"(x));
    return r;
}
__device__ __forceinline__ uint32_t smem_u32(const void* p) {
    uint32_t a;
    asm("{ .reg .u64 t; cvta.to.shared.u64 t, %1; cvt.u32.u64 %0, t; }" : "=r"(a) : "l"(p));
    return a;
}

__device__ __forceinline__ void mma_f16(float* d, const uint32_t* a,
                                        uint32_t b0, uint32_t b1) {
    asm volatile(
        "mma.sync.aligned.m16n8k16.row.col.f32.f16.f16.f32 "
        "{%0,%1,%2,%3}, {%4,%5,%6,%7}, {%8,%9}, {%0,%1,%2,%3};"
        : "+f"(d[0]), "+f"(d[1]), "+f"(d[2]), "+f"(d[3])
        : "r"(a[0]), "r"(a[1]), "r"(a[2]), "r"(a[3]), "r"(b0), "r"(b1));
}

// ---------------------------------------------------------------------------
// Kernel 1: centroids + masked distances + bitonic top-64.
// Grid (NB, 2): blockIdx.y picks which selection this block computes.
// ---------------------------------------------------------------------------
__global__ void __launch_bounds__(NA) select_kernel(const float* __restrict__ coords,
                                                   const void*  __restrict__ ligp) {
    const int b    = blockIdx.x;
    const int pass = blockIdx.y;
    const int t    = threadIdx.x;

    __shared__ float sv[NA];
    __shared__ int   si[NA];
    __shared__ float s_warp[16][7];
    __shared__ float s_cent[6];

    const float* fl = (const float*)ligp;
    const unsigned char* ul = (const unsigned char*)ligp;
    const int mode = (fl[0] == 1.0f) ? 2 : ((ul[1] != 0) ? 0 : 1);

    const int a = b * NA + t;
    const float cx = coords[(size_t)a * 3 + 0];
    const float cy = coords[(size_t)a * 3 + 1];
    const float cz = coords[(size_t)a * 3 + 2];

    bool lig;
    if (mode == 0)      lig = ul[a] != 0;
    else if (mode == 1) lig = ((const int*)ligp)[a] != 0;
    else                lig = fl[a] != 0.0f;
    const float w = lig ? 1.0f : 0.0f;

    float r[7];
    r[0] = cx * w;          r[1] = cy * w;          r[2] = cz * w;
    r[3] = cx * (1.f - w);  r[4] = cy * (1.f - w);  r[5] = cz * (1.f - w);
    r[6] = w;

    #pragma unroll
    for (int o = 16; o > 0; o >>= 1) {
        #pragma unroll
        for (int i = 0; i < 7; i++)
            r[i] += __shfl_down_sync(0xffffffff, r[i], o);
    }
    if ((t & 31) == 0) {
        #pragma unroll
        for (int i = 0; i < 7; i++) s_warp[t >> 5][i] = r[i];
    }
    __syncthreads();
    if (t == 0) {
        float s[7];
        #pragma unroll
        for (int i = 0; i < 7; i++) s[i] = 0.f;
        for (int wI = 0; wI < 16; wI++) {
            #pragma unroll
            for (int i = 0; i < 7; i++) s[i] += s_warp[wI][i];
        }
        const float cl = s[6];
        const float cp = (float)NA - cl;
        s_cent[0] = s[0] / cl;  s_cent[1] = s[1] / cl;  s_cent[2] = s[2] / cl;
        s_cent[3] = s[3] / cp;  s_cent[4] = s[4] / cp;  s_cent[5] = s[5] / cp;
    }
    __syncthreads();

    float dsel;
    if (pass == 0) {
        const float dx = cx - s_cent[0], dy = cy - s_cent[1], dz = cz - s_cent[2];
        const float d = sqrtf(dx * dx + dy * dy + dz * dz);
        dsel = lig ? FLT_MAX : d;
    } else {
        const float dx = cx - s_cent[3], dy = cy - s_cent[4], dz = cz - s_cent[5];
        const float d = sqrtf(dx * dx + dy * dy + dz * dz);
        dsel = lig ? d : FLT_MAX;
    }

    sv[t] = dsel;
    si[t] = t;
    __syncthreads();
    #pragma unroll 1
    for (int k = 2; k <= NA; k <<= 1) {
        #pragma unroll 1
        for (int j = k >> 1; j > 0; j >>= 1) {
            const int ixj = t ^ j;
            const float v0 = sv[t];
            const float v1 = sv[ixj];
            const int   i1 = si[ixj];
            const bool up = ((t & k) == 0);
            const bool takeOther = ((t < ixj) == up) ? (v0 > v1) : (v0 < v1);
            __syncthreads();
            if (takeOther) { sv[t] = v1; si[t] = i1; }
            __syncthreads();
        }
    }
    if (t < KSEL) g_idx[b * SEL + pass * KSEL + t] = b * NA + si[t];
}

// ---------------------------------------------------------------------------
// Kernel 2a: W -> B fragment layout (fp16 hi/lo packed per uint4)
// ---------------------------------------------------------------------------
__global__ void __launch_bounds__(256) conv_w_kernel(const float* __restrict__ W) {
    const int idx  = blockIdx.x * 256 + threadIdx.x;   // < NK16*128*32
    const int lane = idx & 31;
    const int nfg  = (idx >> 5) & 127;
    const int k16  = idx >> 12;

    const int n  = nfg * 8 + (lane >> 2);
    const int k0 = k16 * 16 + (lane & 3) * 2;
    const float2 x0 = *(const float2*)(W + (size_t)n * Dh + k0);
    const float2 x1 = *(const float2*)(W + (size_t)n * Dh + k0 + 8);

    uint4 o;
    o.x = pack_h(x0.x, x0.y);
    o.y = pack_h(x1.x, x1.y);
    o.z = pack_h_lo(o.x, x0.x, x0.y);
    o.w = pack_h_lo(o.y, x1.x, x1.y);
    g_Bf[idx] = o;
}

// ---------------------------------------------------------------------------
// Kernel 2b: gather selected h rows -> A fragment layout (single fp16)
// ---------------------------------------------------------------------------
__global__ void __launch_bounds__(256) conv_h_kernel(const float* __restrict__ h) {
    const int idx  = blockIdx.x * 256 + threadIdx.x;   // < NB*NK16*8*32
    const int lane = idx & 31;
    const int mf   = (idx >> 5) & 7;
    const int k16  = (idx >> 8) & 63;
    const int b    = idx >> 14;

    const int r0 = mf * 16 + (lane >> 2);
    const int gr0 = g_idx[b * SEL + r0];
    const int gr1 = g_idx[b * SEL + r0 + 8];
    const int k0 = k16 * 16 + (lane & 3) * 2;

    const float2 x00 = *(const float2*)(h + (size_t)gr0 * Dh + k0);
    const float2 x10 = *(const float2*)(h + (size_t)gr1 * Dh + k0);
    const float2 x01 = *(const float2*)(h + (size_t)gr0 * Dh + k0 + 8);
    const float2 x11 = *(const float2*)(h + (size_t)gr1 * Dh + k0 + 8);

    uint4 o;
    o.x = pack_h(x00.x, x00.y);
    o.y = pack_h(x10.x, x10.y);
    o.z = pack_h(x01.x, x01.y);
    o.w = pack_h(x11.x, x11.y);
    g_Af[idx] = o;
}

// ---------------------------------------------------------------------------
// Kernel 3: fp16 2-product tensor GEMM + tanh + v-dot.
// R10 shape: 256 threads = 8 warps (wm 0..1 x wn 0..3), warp tile 64x32,
// block tile 128x128, grid (8, 256), 2 co-resident blocks/SM.
// NEW: warp-private cp.async double-buffer pipeline (depth 2), ZERO barriers
// in the k-loop -> warp drift preserved, global latency hidden in SMEM.
// Per-warp stage: 8 frags x 32 lanes x 16B = 4KB; 8 warps x 2 stages = 64KB.
// ---------------------------------------------------------------------------
__global__ void __launch_bounds__(256, 2) gemm_kernel(const float* __restrict__ bias,
                                                      const float* __restrict__ vvec) {
    extern __shared__ uint4 sbuf[];   // [2][8 warps][8 frags][32 lanes]

    const int ecp  = blockIdx.x;   // 0..7 (128-wide col chunk)
    const int b    = blockIdx.y;
    const int tid  = threadIdx.x;
    const int lane = tid & 31;
    const int wid  = tid >> 5;     // 0..7
    const int wm   = wid >> 2;     // 0..1
    const int wn   = wid & 3;      // 0..3

    __shared__ float s_b[128];
    __shared__ float s_v[128];
    __shared__ float s_part[4][128];

    if (tid < 128) {
        s_b[tid] = bias[ecp * 128 + tid];
        s_v[tid] = vvec[ecp * 128 + tid];
    }
    __syncthreads();

    const uint4* pA = g_Af + ((size_t)b * NK16 * 8 + wm * 4) * 32 + lane;
    const uint4* pB = g_Bf + ((size_t)(ecp * 16 + wn * 4)) * 32 + lane;

    // this thread's slot base (uint4 index) within a stage
    const int slot = (wid * 8) * 32 + lane;            // frag f at + f*32
    const uint32_t sa0 = smem_u32(sbuf + slot);                    // stage 0
    const uint32_t sa1 = smem_u32(sbuf + (8 * 8 * 32) + slot);     // stage 1

    // issue cp.async for k16 stage s into buffer buf (0/1)
    auto issue_stage = [&](int s, uint32_t sab) {
        const uint4* srcA = pA + s * 256;
        const uint4* srcB = pB + s * 4096;
        #pragma unroll
        for (int mf = 0; mf < 4; mf++)
            asm volatile("cp.async.cg.shared.global [%0], [%1], 16;"
                         :: "r"(sab + mf * (32 * 16)), "l"(srcA + mf * 32) : "memory");
        #pragma unroll
        for (int nf = 0; nf < 4; nf++)
            asm volatile("cp.async.cg.shared.global [%0], [%1], 16;"
                         :: "r"(sab + (4 + nf) * (32 * 16)), "l"(srcB + nf * 32) : "memory");
        asm volatile("cp.async.commit_group;" ::: "memory");
    };

    float acc[4][4][4];
    #pragma unroll
    for (int mf = 0; mf < 4; mf++)
        #pragma unroll
        for (int nf = 0; nf < 4; nf++)
            #pragma unroll
            for (int r = 0; r < 4; r++) acc[mf][nf][r] = 0.f;

    issue_stage(0, sa0);
    issue_stage(1, sa1);

    const uint4* sbase0 = sbuf + slot;
    const uint4* sbase1 = sbuf + (8 * 8 * 32) + slot;

    #pragma unroll 1
    for (int s = 0; s < NK16; s++) {
        if (s < NK16 - 1)
            asm volatile("cp.async.wait_group 1;" ::: "memory");
        else
            asm volatile("cp.async.wait_group 0;" ::: "memory");

        const uint4* sb = (s & 1) ? sbase1 : sbase0;
        uint32_t af[4][4];
        uint4 bb[4];
        #pragma unroll
        for (int mf = 0; mf < 4; mf++)
            *(uint4*)af[mf] = sb[mf * 32];
        #pragma unroll
        for (int nf = 0; nf < 4; nf++)
            bb[nf] = sb[(4 + nf) * 32];

        // refill this buffer with stage s+2 (after our own LDS reads above)
        if (s + 2 < NK16)
            issue_stage(s + 2, (s & 1) ? sa1 : sa0);

        // pass 1: A * B_hi  (16 independent accumulators)
        #pragma unroll
        for (int nf = 0; nf < 4; nf++)
            #pragma unroll
            for (int mf = 0; mf < 4; mf++)
                mma_f16(acc[mf][nf], af[mf], bb[nf].x, bb[nf].y);
        // pass 2: A * B_lo
        #pragma unroll
        for (int nf = 0; nf < 4; nf++)
            #pragma unroll
            for (int mf = 0; mf < 4; mf++)
                mma_f16(acc[mf][nf], af[mf], bb[nf].z, bb[nf].w);
    }

    // Epilogue: part[row] = sum_cols v[col]*tanh(acc + b[col])
    #pragma unroll
    for (int mf = 0; mf < 4; mf++) {
        float s0 = 0.f, s1 = 0.f;
        #pragma unroll
        for (int nf = 0; nf < 4; nf++) {
            const int cl = wn * 32 + nf * 8 + (lane & 3) * 2;
            s0 += s_v[cl]     * fast_tanh(acc[mf][nf][0] + s_b[cl]);
            s0 += s_v[cl + 1] * fast_tanh(acc[mf][nf][1] + s_b[cl + 1]);
            s1 += s_v[cl]     * fast_tanh(acc[mf][nf][2] + s_b[cl]);
            s1 += s_v[cl + 1] * fast_tanh(acc[mf][nf][3] + s_b[cl + 1]);
        }
        s0 += __shfl_xor_sync(0xffffffff, s0, 1);
        s0 += __shfl_xor_sync(0xffffffff, s0, 2);
        s1 += __shfl_xor_sync(0xffffffff, s1, 1);
        s1 += __shfl_xor_sync(0xffffffff, s1, 2);
        if ((lane & 3) == 0) {
            const int r = wm * 64 + mf * 16 + (lane >> 2);
            s_part[wn][r]     = s0;
            s_part[wn][r + 8] = s1;
        }
    }
    __syncthreads();

    if (tid < 128) {
        const float s = s_part[0][tid] + s_part[1][tid] + s_part[2][tid] + s_part[3][tid];
        g_part[((size_t)ecp * NB + b) * SEL + tid] = s;
    }
}

// ---------------------------------------------------------------------------
// Kernel 4: softmax + alpha-weighted gather sum.
// Grid (NB, 2), 128 threads: blockIdx.y picks which 512-dim half this block
// pools (softmax recomputed redundantly; doubles gather parallelism).
// ---------------------------------------------------------------------------
__global__ void __launch_bounds__(128) pool_kernel(const float* __restrict__ h,
                                                   float* __restrict__ out) {
    const int b  = blockIdx.x;
    const int hy = blockIdx.y;    // 0..1
    const int t  = threadIdx.x;   // 0..127

    __shared__ float s_al[SEL];
    __shared__ int   s_ix[SEL];
    __shared__ float s_tmp[2];

    {
        float s = 0.f;
        #pragma unroll
        for (int c = 0; c < NPART; c++)
            s += g_part[((size_t)c * NB + b) * SEL + t];
        s_al[t] = s;
        s_ix[t] = g_idx[b * SEL + t];
    }
    __syncthreads();
    if (t == 0) {
        float m = -FLT_MAX;
        for (int k = 0; k < SEL; k++) m = fmaxf(m, s_al[k]);
        s_tmp[0] = m;
    }
    __syncthreads();
    s_al[t] = expf(s_al[t] - s_tmp[0]);
    __syncthreads();
    if (t == 0) {
        float s = 0.f;
        for (int k = 0; k < SEL; k++) s += s_al[k];
        s_tmp[1] = 1.f / s;
    }
    __syncthreads();
    s_al[t] *= s_tmp[1];
    __syncthreads();

    const int d0 = hy * 512 + t * 4;
    float4 acc = make_float4(0.f, 0.f, 0.f, 0.f);
    #pragma unroll 8
    for (int k = 0; k < SEL; k++) {
        const float al = s_al[k];
        const float4 hv = __ldg((const float4*)(h + (size_t)s_ix[k] * Dh + d0));
        acc.x += al * hv.x;  acc.y += al * hv.y;
        acc.z += al * hv.z;  acc.w += al * hv.w;
    }
    *(float4*)(out + (size_t)b * Dh + d0) = acc;
}

// ---------------------------------------------------------------------------
extern "C" void kernel_launch(void* const* d_in, const int* in_sizes, int n_in,
                              void* d_out, int out_size) {
    const float* h      = (const float*)d_in[0];
    const float* coords = (const float*)d_in[1];
    const void*  lig    = d_in[3];
    const float* W      = (const float*)d_in[4];
    const float* bias   = (const float*)d_in[5];
    const float* vvec   = (const float*)d_in[6];
    float* out = (float*)d_out;

    static int smem_set = 0;
    if (!smem_set) {
        cudaFuncSetAttribute(gemm_kernel, cudaFuncAttributeMaxDynamicSharedMemorySize,
                             65536);
        smem_set = 1;
    }

    dim3 gsel(NB, 2);
    select_kernel<<<gsel, NA>>>(coords, lig);
    conv_w_kernel<<<(NK16 * 128 * 32) / 256, 256>>>(W);
    conv_h_kernel<<<(NB * NK16 * 8 * 32) / 256, 256>>>(h);
    dim3 g3(NPART, NB);
    gemm_kernel<<<g3, 256, 65536>>>(bias, vvec);
    dim3 g4(NB, 2);
    pool_kernel<<<g4, 128>>>(h, out);
}

// round 13
// speedup vs baseline: 1.1188x; 1.0235x over previous
#include <cuda_runtime.h>
#include <cuda_fp16.h>
#include <math.h>
#include <float.h>
#include <stdint.h>

// Problem shape (fixed)
#define Dh    1024
#define NB    256
#define NA    512
#define KSEL  64
#define SEL   128
#define NPART 8        // gemm N-chunks of 128
#define NK16  64       // Dh / 16
#define STG   2048     // uint4 per pipeline stage (8 warps * 8 frags * 32 lanes)

// Scratch (device globals)
__device__ int   g_idx[NB * SEL];
__device__ float g_part[NPART * NB * SEL];
// fp16 operands in m16n8k16 fragment layout:
//  A (single fp16): [b][k16(64)][mf(8)][lane(32)] -> uint4 {a0,a1,a2,a3}  (67 MB)
//  B (hi/lo split): [k16(64)][nfg(128)][lane(32)] -> uint4 {bh0,bh1,bl0,bl1} (4 MB)
__device__ uint4 g_Af[NB * NK16 * 8 * 32];
__device__ uint4 g_Bf[NK16 * 128 * 32];

// ---------------------------------------------------------------------------
__device__ __forceinline__ uint32_t pack_h(float x0, float x1) {
    const __half2 h = __floats2half2_rn(x0, x1);
    return *(const uint32_t*)&h;
}
__device__ __forceinline__ uint32_t pack_h_lo(uint32_t hi_pack, float x0, float x1) {
    const __half2 h = *(const __half2*)&hi_pack;
    const float2 f = __half22float2(h);
    return pack_h(x0 - f.x, x1 - f.y);
}
__device__ __forceinline__ float fast_tanh(float x) {
    float r;
    asm("tanh.approx.f32 %0, %1;" : "=f"(r) : "f"(x));
    return r;
}
__device__ __forceinline__ uint32_t smem_u32(const void* p) {
    uint32_t a;
    asm("{ .reg .u64 t; cvta.to.shared.u64 t, %1; cvt.u32.u64 %0, t; }" : "=r"(a) : "l"(p));
    return a;
}

__device__ __forceinline__ void mma_f16(float* d, const uint32_t* a,
                                        uint32_t b0, uint32_t b1) {
    asm volatile(
        "mma.sync.aligned.m16n8k16.row.col.f32.f16.f16.f32 "
        "{%0,%1,%2,%3}, {%4,%5,%6,%7}, {%8,%9}, {%0,%1,%2,%3};"
        : "+f"(d[0]), "+f"(d[1]), "+f"(d[2]), "+f"(d[3])
        : "r"(a[0]), "r"(a[1]), "r"(a[2]), "r"(a[3]), "r"(b0), "r"(b1));
}

// ---------------------------------------------------------------------------
// Kernel 1: centroids + masked distances + bitonic top-64.
// Grid (NB, 2): blockIdx.y picks which selection this block computes.
// ---------------------------------------------------------------------------
__global__ void __launch_bounds__(NA) select_kernel(const float* __restrict__ coords,
                                                   const void*  __restrict__ ligp) {
    const int b    = blockIdx.x;
    const int pass = blockIdx.y;
    const int t    = threadIdx.x;

    __shared__ float sv[NA];
    __shared__ int   si[NA];
    __shared__ float s_warp[16][7];
    __shared__ float s_cent[6];

    const float* fl = (const float*)ligp;
    const unsigned char* ul = (const unsigned char*)ligp;
    const int mode = (fl[0] == 1.0f) ? 2 : ((ul[1] != 0) ? 0 : 1);

    const int a = b * NA + t;
    const float cx = coords[(size_t)a * 3 + 0];
    const float cy = coords[(size_t)a * 3 + 1];
    const float cz = coords[(size_t)a * 3 + 2];

    bool lig;
    if (mode == 0)      lig = ul[a] != 0;
    else if (mode == 1) lig = ((const int*)ligp)[a] != 0;
    else                lig = fl[a] != 0.0f;
    const float w = lig ? 1.0f : 0.0f;

    float r[7];
    r[0] = cx * w;          r[1] = cy * w;          r[2] = cz * w;
    r[3] = cx * (1.f - w);  r[4] = cy * (1.f - w);  r[5] = cz * (1.f - w);
    r[6] = w;

    #pragma unroll
    for (int o = 16; o > 0; o >>= 1) {
        #pragma unroll
        for (int i = 0; i < 7; i++)
            r[i] += __shfl_down_sync(0xffffffff, r[i], o);
    }
    if ((t & 31) == 0) {
        #pragma unroll
        for (int i = 0; i < 7; i++) s_warp[t >> 5][i] = r[i];
    }
    __syncthreads();
    if (t == 0) {
        float s[7];
        #pragma unroll
        for (int i = 0; i < 7; i++) s[i] = 0.f;
        for (int wI = 0; wI < 16; wI++) {
            #pragma unroll
            for (int i = 0; i < 7; i++) s[i] += s_warp[wI][i];
        }
        const float cl = s[6];
        const float cp = (float)NA - cl;
        s_cent[0] = s[0] / cl;  s_cent[1] = s[1] / cl;  s_cent[2] = s[2] / cl;
        s_cent[3] = s[3] / cp;  s_cent[4] = s[4] / cp;  s_cent[5] = s[5] / cp;
    }
    __syncthreads();

    float dsel;
    if (pass == 0) {
        const float dx = cx - s_cent[0], dy = cy - s_cent[1], dz = cz - s_cent[2];
        const float d = sqrtf(dx * dx + dy * dy + dz * dz);
        dsel = lig ? FLT_MAX : d;
    } else {
        const float dx = cx - s_cent[3], dy = cy - s_cent[4], dz = cz - s_cent[5];
        const float d = sqrtf(dx * dx + dy * dy + dz * dz);
        dsel = lig ? d : FLT_MAX;
    }

    sv[t] = dsel;
    si[t] = t;
    __syncthreads();
    #pragma unroll 1
    for (int k = 2; k <= NA; k <<= 1) {
        #pragma unroll 1
        for (int j = k >> 1; j > 0; j >>= 1) {
            const int ixj = t ^ j;
            const float v0 = sv[t];
            const float v1 = sv[ixj];
            const int   i1 = si[ixj];
            const bool up = ((t & k) == 0);
            const bool takeOther = ((t < ixj) == up) ? (v0 > v1) : (v0 < v1);
            __syncthreads();
            if (takeOther) { sv[t] = v1; si[t] = i1; }
            __syncthreads();
        }
    }
    if (t < KSEL) g_idx[b * SEL + pass * KSEL + t] = b * NA + si[t];
}

// ---------------------------------------------------------------------------
// Kernel 2a: W -> B fragment layout (fp16 hi/lo packed per uint4)
// ---------------------------------------------------------------------------
__global__ void __launch_bounds__(256) conv_w_kernel(const float* __restrict__ W) {
    const int idx  = blockIdx.x * 256 + threadIdx.x;   // < NK16*128*32
    const int lane = idx & 31;
    const int nfg  = (idx >> 5) & 127;
    const int k16  = idx >> 12;

    const int n  = nfg * 8 + (lane >> 2);
    const int k0 = k16 * 16 + (lane & 3) * 2;
    const float2 x0 = *(const float2*)(W + (size_t)n * Dh + k0);
    const float2 x1 = *(const float2*)(W + (size_t)n * Dh + k0 + 8);

    uint4 o;
    o.x = pack_h(x0.x, x0.y);
    o.y = pack_h(x1.x, x1.y);
    o.z = pack_h_lo(o.x, x0.x, x0.y);
    o.w = pack_h_lo(o.y, x1.x, x1.y);
    g_Bf[idx] = o;
}

// ---------------------------------------------------------------------------
// Kernel 2b: gather selected h rows -> A fragment layout (single fp16)
// ---------------------------------------------------------------------------
__global__ void __launch_bounds__(256) conv_h_kernel(const float* __restrict__ h) {
    const int idx  = blockIdx.x * 256 + threadIdx.x;   // < NB*NK16*8*32
    const int lane = idx & 31;
    const int mf   = (idx >> 5) & 7;
    const int k16  = (idx >> 8) & 63;
    const int b    = idx >> 14;

    const int r0 = mf * 16 + (lane >> 2);
    const int gr0 = g_idx[b * SEL + r0];
    const int gr1 = g_idx[b * SEL + r0 + 8];
    const int k0 = k16 * 16 + (lane & 3) * 2;

    const float2 x00 = *(const float2*)(h + (size_t)gr0 * Dh + k0);
    const float2 x10 = *(const float2*)(h + (size_t)gr1 * Dh + k0);
    const float2 x01 = *(const float2*)(h + (size_t)gr0 * Dh + k0 + 8);
    const float2 x11 = *(const float2*)(h + (size_t)gr1 * Dh + k0 + 8);

    uint4 o;
    o.x = pack_h(x00.x, x00.y);
    o.y = pack_h(x10.x, x10.y);
    o.z = pack_h(x01.x, x01.y);
    o.w = pack_h(x11.x, x11.y);
    g_Af[idx] = o;
}

// ---------------------------------------------------------------------------
// Kernel 3: fp16 2-product tensor GEMM + tanh + v-dot.
// R12 dataflow with 3-stage warp-private cp.async pipeline (no barriers in
// the k-loop). 256 threads = 8 warps (wm 0..1 x wn 0..3), warp tile 64x32,
// block tile 128x128, grid (8, 256), 2 blocks/SM, 96KB dynamic SMEM/block.
// ---------------------------------------------------------------------------
__global__ void __launch_bounds__(256, 2) gemm_kernel(const float* __restrict__ bias,
                                                      const float* __restrict__ vvec) {
    extern __shared__ uint4 sbuf[];   // [3][8 warps][8 frags][32 lanes]

    const int ecp  = blockIdx.x;   // 0..7 (128-wide col chunk)
    const int b    = blockIdx.y;
    const int tid  = threadIdx.x;
    const int lane = tid & 31;
    const int wid  = tid >> 5;     // 0..7
    const int wm   = wid >> 2;     // 0..1
    const int wn   = wid & 3;      // 0..3

    __shared__ float s_b[128];
    __shared__ float s_v[128];
    __shared__ float s_part[4][128];

    if (tid < 128) {
        s_b[tid] = bias[ecp * 128 + tid];
        s_v[tid] = vvec[ecp * 128 + tid];
    }
    __syncthreads();

    const uint4* pA = g_Af + ((size_t)b * NK16 * 8 + wm * 4) * 32 + lane;
    const uint4* pB = g_Bf + ((size_t)(ecp * 16 + wn * 4)) * 32 + lane;

    // this thread's slot base (uint4 index) within a stage
    const int slot = (wid * 8) * 32 + lane;            // frag f at + f*32

    // issue cp.async for k16 stage s into SMEM address sab
    auto issue_stage = [&](int s, uint32_t sab) {
        const uint4* srcA = pA + s * 256;
        const uint4* srcB = pB + s * 4096;
        #pragma unroll
        for (int mf = 0; mf < 4; mf++)
            asm volatile("cp.async.cg.shared.global [%0], [%1], 16;"
                         :: "r"(sab + mf * (32 * 16)), "l"(srcA + mf * 32) : "memory");
        #pragma unroll
        for (int nf = 0; nf < 4; nf++)
            asm volatile("cp.async.cg.shared.global [%0], [%1], 16;"
                         :: "r"(sab + (4 + nf) * (32 * 16)), "l"(srcB + nf * 32) : "memory");
        asm volatile("cp.async.commit_group;" ::: "memory");
    };

    float acc[4][4][4];
    #pragma unroll
    for (int mf = 0; mf < 4; mf++)
        #pragma unroll
        for (int nf = 0; nf < 4; nf++)
            #pragma unroll
            for (int r = 0; r < 4; r++) acc[mf][nf][r] = 0.f;

    // 3 rotating stage buffers (register-resident pointers/addresses)
    const uint4* c0 = sbuf + slot;
    const uint4* c1 = sbuf + STG + slot;
    const uint4* c2 = sbuf + 2 * STG + slot;
    uint32_t a0 = smem_u32(c0);
    uint32_t a1 = smem_u32(c1);
    uint32_t a2 = smem_u32(c2);

    issue_stage(0, a0);
    issue_stage(1, a1);
    issue_stage(2, a2);

    #pragma unroll 1
    for (int s = 0; s < NK16; s++) {
        if (s < NK16 - 2)
            asm volatile("cp.async.wait_group 2;" ::: "memory");
        else if (s == NK16 - 2)
            asm volatile("cp.async.wait_group 1;" ::: "memory");
        else
            asm volatile("cp.async.wait_group 0;" ::: "memory");

        uint32_t af[4][4];
        uint4 bb[4];
        #pragma unroll
        for (int mf = 0; mf < 4; mf++)
            *(uint4*)af[mf] = c0[mf * 32];
        #pragma unroll
        for (int nf = 0; nf < 4; nf++)
            bb[nf] = c0[(4 + nf) * 32];

        // refill this buffer with stage s+3 (after our own LDS reads above)
        if (s + 3 < NK16)
            issue_stage(s + 3, a0);

        // pass 1: A * B_hi  (16 independent accumulators)
        #pragma unroll
        for (int nf = 0; nf < 4; nf++)
            #pragma unroll
            for (int mf = 0; mf < 4; mf++)
                mma_f16(acc[mf][nf], af[mf], bb[nf].x, bb[nf].y);
        // pass 2: A * B_lo
        #pragma unroll
        for (int nf = 0; nf < 4; nf++)
            #pragma unroll
            for (int mf = 0; mf < 4; mf++)
                mma_f16(acc[mf][nf], af[mf], bb[nf].z, bb[nf].w);

        // rotate buffers
        const uint4* ct = c0; c0 = c1; c1 = c2; c2 = ct;
        const uint32_t at = a0; a0 = a1; a1 = a2; a2 = at;
    }

    // Epilogue: part[row] = sum_cols v[col]*tanh(acc + b[col])
    #pragma unroll
    for (int mf = 0; mf < 4; mf++) {
        float s0 = 0.f, s1 = 0.f;
        #pragma unroll
        for (int nf = 0; nf < 4; nf++) {
            const int cl = wn * 32 + nf * 8 + (lane & 3) * 2;
            s0 += s_v[cl]     * fast_tanh(acc[mf][nf][0] + s_b[cl]);
            s0 += s_v[cl + 1] * fast_tanh(acc[mf][nf][1] + s_b[cl + 1]);
            s1 += s_v[cl]     * fast_tanh(acc[mf][nf][2] + s_b[cl]);
            s1 += s_v[cl + 1] * fast_tanh(acc[mf][nf][3] + s_b[cl + 1]);
        }
        s0 += __shfl_xor_sync(0xffffffff, s0, 1);
        s0 += __shfl_xor_sync(0xffffffff, s0, 2);
        s1 += __shfl_xor_sync(0xffffffff, s1, 1);
        s1 += __shfl_xor_sync(0xffffffff, s1, 2);
        if ((lane & 3) == 0) {
            const int r = wm * 64 + mf * 16 + (lane >> 2);
            s_part[wn][r]     = s0;
            s_part[wn][r + 8] = s1;
        }
    }
    __syncthreads();

    if (tid < 128) {
        const float s = s_part[0][tid] + s_part[1][tid] + s_part[2][tid] + s_part[3][tid];
        g_part[((size_t)ecp * NB + b) * SEL + tid] = s;
    }
}

// ---------------------------------------------------------------------------
// Kernel 4: softmax + alpha-weighted gather sum.
// Grid (NB, 2), 128 threads: blockIdx.y picks which 512-dim half this block
// pools (softmax recomputed redundantly; doubles gather parallelism).
// ---------------------------------------------------------------------------
__global__ void __launch_bounds__(128) pool_kernel(const float* __restrict__ h,
                                                   float* __restrict__ out) {
    const int b  = blockIdx.x;
    const int hy = blockIdx.y;    // 0..1
    const int t  = threadIdx.x;   // 0..127

    __shared__ float s_al[SEL];
    __shared__ int   s_ix[SEL];
    __shared__ float s_tmp[2];

    {
        float s = 0.f;
        #pragma unroll
        for (int c = 0; c < NPART; c++)
            s += g_part[((size_t)c * NB + b) * SEL + t];
        s_al[t] = s;
        s_ix[t] = g_idx[b * SEL + t];
    }
    __syncthreads();
    if (t == 0) {
        float m = -FLT_MAX;
        for (int k = 0; k < SEL; k++) m = fmaxf(m, s_al[k]);
        s_tmp[0] = m;
    }
    __syncthreads();
    s_al[t] = expf(s_al[t] - s_tmp[0]);
    __syncthreads();
    if (t == 0) {
        float s = 0.f;
        for (int k = 0; k < SEL; k++) s += s_al[k];
        s_tmp[1] = 1.f / s;
    }
    __syncthreads();
    s_al[t] *= s_tmp[1];
    __syncthreads();

    const int d0 = hy * 512 + t * 4;
    float4 acc = make_float4(0.f, 0.f, 0.f, 0.f);
    #pragma unroll 8
    for (int k = 0; k < SEL; k++) {
        const float al = s_al[k];
        const float4 hv = __ldg((const float4*)(h + (size_t)s_ix[k] * Dh + d0));
        acc.x += al * hv.x;  acc.y += al * hv.y;
        acc.z += al * hv.z;  acc.w += al * hv.w;
    }
    *(float4*)(out + (size_t)b * Dh + d0) = acc;
}

// ---------------------------------------------------------------------------
extern "C" void kernel_launch(void* const* d_in, const int* in_sizes, int n_in,
                              void* d_out, int out_size) {
    const float* h      = (const float*)d_in[0];
    const float* coords = (const float*)d_in[1];
    const void*  lig    = d_in[3];
    const float* W      = (const float*)d_in[4];
    const float* bias   = (const float*)d_in[5];
    const float* vvec   = (const float*)d_in[6];
    float* out = (float*)d_out;

    static int smem_set = 0;
    if (!smem_set) {
        cudaFuncSetAttribute(gemm_kernel, cudaFuncAttributeMaxDynamicSharedMemorySize,
                             3 * STG * 16);
        smem_set = 1;
    }

    dim3 gsel(NB, 2);
    select_kernel<<<gsel, NA>>>(coords, lig);
    conv_w_kernel<<<(NK16 * 128 * 32) / 256, 256>>>(W);
    conv_h_kernel<<<(NB * NK16 * 8 * 32) / 256, 256>>>(h);
    dim3 g3(NPART, NB);
    gemm_kernel<<<g3, 256, 3 * STG * 16>>>(bias, vvec);
    dim3 g4(NB, 2);
    pool_kernel<<<g4, 128>>>(h, out);
}